// round 9
// baseline (speedup 1.0000x reference)
#include <cuda_runtime.h>
#include <cuda_bf16.h>
#include <stdint.h>

#define BB   4
#define DIM  64
#define CDIM 128
#define DD   64
#define HH   64
#define WW   64
#define NSP  (DD*HH*WW)
#define HW   (HH*WW)

__device__ __nv_bfloat16 g_q[(size_t)BB * DIM * NSP];
__device__ __nv_bfloat16 g_k[(size_t)BB * DIM * NSP];
__device__ __nv_bfloat16 g_v[(size_t)BB * DIM * NSP];

__device__ __forceinline__ void mma16816(float c[4], const uint32_t a[4],
                                         uint32_t b0, uint32_t b1) {
    asm volatile(
        "mma.sync.aligned.m16n8k16.row.col.f32.bf16.bf16.f32 "
        "{%0,%1,%2,%3}, {%4,%5,%6,%7}, {%8,%9}, {%0,%1,%2,%3};\n"
        : "+f"(c[0]), "+f"(c[1]), "+f"(c[2]), "+f"(c[3])
        : "r"(a[0]), "r"(a[1]), "r"(a[2]), "r"(a[3]), "r"(b0), "r"(b1));
}

__device__ __forceinline__ uint32_t packbf(float a, float b) {
    __nv_bfloat162 p = __floats2bfloat162_rn(a, b);
    return *reinterpret_cast<uint32_t*>(&p);
}

__device__ __forceinline__ uint32_t smaddr(const void* p) {
    return (uint32_t)__cvta_generic_to_shared(p);
}

__device__ __forceinline__ void ldsm4(uint32_t& r0, uint32_t& r1,
                                      uint32_t& r2, uint32_t& r3, uint32_t a) {
    asm volatile("ldmatrix.sync.aligned.m8n8.x4.shared.b16 {%0,%1,%2,%3},[%4];\n"
                 : "=r"(r0), "=r"(r1), "=r"(r2), "=r"(r3) : "r"(a));
}

__device__ __forceinline__ void ldsm4t(uint32_t& r0, uint32_t& r1,
                                       uint32_t& r2, uint32_t& r3, uint32_t a) {
    asm volatile("ldmatrix.sync.aligned.m8n8.x4.trans.shared.b16 {%0,%1,%2,%3},[%4];\n"
                 : "=r"(r0), "=r"(r1), "=r"(r2), "=r"(r3) : "r"(a));
}

__device__ __forceinline__ void stsm4(uint32_t a, uint32_t r0, uint32_t r1,
                                      uint32_t r2, uint32_t r3) {
    asm volatile("stmatrix.sync.aligned.m8n8.x4.shared.b16 [%0],{%1,%2,%3,%4};\n"
                 :: "r"(a), "r"(r0), "r"(r1), "r"(r2), "r"(r3) : "memory");
}

__device__ __forceinline__ void cpasync16(uint32_t s, const void* g) {
    asm volatile("cp.async.cg.shared.global [%0], [%1], 16;\n" :: "r"(s), "l"(g));
}

__device__ __forceinline__ uint4 ldpack8(const float* src) {
    float4 a = *reinterpret_cast<const float4*>(src);
    float4 b = *reinterpret_cast<const float4*>(src + 4);
    return make_uint4(packbf(a.x, a.y), packbf(a.z, a.w),
                      packbf(b.x, b.y), packbf(b.z, b.w));
}

// ---------------------------------------------------------------------------
// Pass 1a: Q = Wq[64x64] * X + bq. 256 thr, weights resident, 4 N-tiles of 128.
// Prefetch converts to bf16 at load (uint4 r[2][4] = 32 regs). Output staging
// aliases Xs. stmatrix epilogue + coalesced STG.128.
// ---------------------------------------------------------------------------
#define QT 4
__global__ void __launch_bounds__(256, 4) conv_q_kernel(
    const float* __restrict__ x, const float* __restrict__ wq,
    const float* __restrict__ bq)
{
    __shared__ __align__(16) __nv_bfloat16 Ws[64 * 72];
    __shared__ __align__(16) __nv_bfloat16 Xs[64 * 136];   // input AND output staging
    __shared__ float bs[64];

    const int tid = threadIdx.x;
    const int b  = blockIdx.y;
    const float* xb = x + (size_t)b * DIM * NSP;
    __nv_bfloat16* qb = g_q + (size_t)b * DIM * NSP;

    #pragma unroll
    for (int i = tid; i < 64 * 8; i += 256) {
        const int o = i >> 3, c8 = (i & 7) * 8;
        *reinterpret_cast<uint4*>(&Ws[o * 72 + c8]) = ldpack8(&wq[o * 64 + c8]);
    }
    if (tid < 64) bs[tid] = bq[tid];

    const int warp = tid >> 5, lane = tid & 31;
    const int mw = warp >> 1, nw = warp & 1;
    const int lr = lane >> 2;
    const int l8  = lane & 7;
    const int lB1 = (lane >> 3) & 1;
    const int lB2 = (lane >> 4) & 1;
    const int m = mw * 16 + lr;

    const uint32_t aBase = smaddr(Ws) +
        ((mw * 16 + lB1 * 8 + l8) * 72 + lB2 * 8) * 2;
    const uint32_t bBase = smaddr(Xs) +
        ((lB1 * 8 + l8) * 136 + nw * 64 + lB2 * 8) * 2;
    const uint32_t oBase = smaddr(Xs) +
        ((mw * 16 + lB1 * 8 + l8) * 136 + nw * 64 + lB2 * 8) * 2;

    int sc_[4], sn_[4];
    #pragma unroll
    for (int j = 0; j < 4; ++j) {
        const int i = tid + j * 256;
        sc_[j] = i >> 4;
        sn_[j] = (i & 15) * 8;
    }

    uint4 r[2][4];
    const int tile0 = blockIdx.x * (QT * 128);
    #pragma unroll
    for (int j = 0; j < 4; ++j)
        r[0][j] = ldpack8(&xb[(size_t)sc_[j] * NSP + tile0 + sn_[j]]);
    __syncthreads();

    const float bi0 = bs[m], bi1 = bs[m + 8];

    #pragma unroll
    for (int t = 0; t < QT; ++t) {
        const int n0 = tile0 + t * 128;
        const int cur = t & 1, nxt = cur ^ 1;
        #pragma unroll
        for (int j = 0; j < 4; ++j)
            *reinterpret_cast<uint4*>(&Xs[sc_[j] * 136 + sn_[j]]) = r[cur][j];
        __syncthreads();

        if (t + 1 < QT) {
            #pragma unroll
            for (int j = 0; j < 4; ++j)
                r[nxt][j] = ldpack8(&xb[(size_t)sc_[j] * NSP + n0 + 128 + sn_[j]]);
        }

        float acc[8][4];
        #pragma unroll
        for (int nf = 0; nf < 8; ++nf)
            #pragma unroll
            for (int e = 0; e < 4; ++e) acc[nf][e] = 0.f;

        #pragma unroll
        for (int kc = 0; kc < 4; ++kc) {
            uint32_t a[4];
            ldsm4(a[0], a[1], a[2], a[3], aBase + kc * 32);
            #pragma unroll
            for (int nfp = 0; nfp < 4; ++nfp) {
                uint32_t b0, b1, b2, b3;
                ldsm4t(b0, b1, b2, b3, bBase + kc * 4352 + nfp * 32);
                mma16816(acc[2 * nfp],     a, b0, b1);
                mma16816(acc[2 * nfp + 1], a, b2, b3);
            }
        }
        __syncthreads();   // all Xs reads done before stsm clobbers it

        #pragma unroll
        for (int nfp = 0; nfp < 4; ++nfp) {
            stsm4(oBase + nfp * 32,
                  packbf(acc[2*nfp][0] + bi0,   acc[2*nfp][1] + bi0),
                  packbf(acc[2*nfp][2] + bi1,   acc[2*nfp][3] + bi1),
                  packbf(acc[2*nfp+1][0] + bi0, acc[2*nfp+1][1] + bi0),
                  packbf(acc[2*nfp+1][2] + bi1, acc[2*nfp+1][3] + bi1));
        }
        __syncthreads();

        #pragma unroll
        for (int i = tid; i < 64 * 16; i += 256) {
            const int row = i >> 4, q8 = (i & 15) * 8;
            uint4 v = *reinterpret_cast<const uint4*>(&Xs[row * 136 + q8]);
            *reinterpret_cast<uint4*>(&qb[(size_t)row * NSP + n0 + q8]) = v;
        }
        __syncthreads();
    }
}

// ---------------------------------------------------------------------------
// Pass 1b: [K;V] = [Wk;Wv][128x128]*CTX + bias. 512 thr, weights resident,
// 4 N-tiles of 128. Prefetch converts early; output staging aliases Xs.
// Dynamic smem ~70KB -> 2-3 CTAs/SM.
// ---------------------------------------------------------------------------
#define KVT 4
#define KV_SMEM_BYTES (2 * 128 * 136 * (int)sizeof(__nv_bfloat16) + 128 * (int)sizeof(float))

__global__ void __launch_bounds__(512, 2) conv_kv_kernel(
    const float* __restrict__ ctx,
    const float* __restrict__ wk, const float* __restrict__ bk,
    const float* __restrict__ wv, const float* __restrict__ bv)
{
    extern __shared__ __align__(16) __nv_bfloat16 sm[];
    __nv_bfloat16* Ws = sm;                  // [o=128][c pitch 136]
    __nv_bfloat16* Xs = sm + 128 * 136;      // input AND output staging
    float* bs = reinterpret_cast<float*>(sm + 2 * 128 * 136);

    const int tid = threadIdx.x;
    const int b = blockIdx.y;
    const float* cb = ctx + (size_t)b * CDIM * NSP;

    #pragma unroll
    for (int i = tid; i < 128 * 16; i += 512) {
        const int o = i >> 4, c8 = (i & 15) * 8;
        const float* src = (o < 64) ? &wk[o * 128 + c8] : &wv[(o - 64) * 128 + c8];
        *reinterpret_cast<uint4*>(&Ws[o * 136 + c8]) = ldpack8(src);
    }
    if (tid < 128) bs[tid] = (tid < 64) ? bk[tid] : bv[tid - 64];

    const int warp = tid >> 5, lane = tid & 31;
    const int mw = warp & 3, nw = warp >> 2;
    const int lr = lane >> 2;
    const int l8  = lane & 7;
    const int lB1 = (lane >> 3) & 1;
    const int lB2 = (lane >> 4) & 1;

    uint32_t aBase[2], oBase[2];
    #pragma unroll
    for (int mi = 0; mi < 2; ++mi) {
        aBase[mi] = smaddr(Ws) +
            ((mw * 32 + mi * 16 + lB1 * 8 + l8) * 136 + lB2 * 8) * 2;
        oBase[mi] = smaddr(Xs) +
            ((mw * 32 + mi * 16 + lB1 * 8 + l8) * 136 + nw * 32 + lB2 * 8) * 2;
    }
    const uint32_t bBase = smaddr(Xs) +
        ((lB1 * 8 + l8) * 136 + nw * 32 + lB2 * 8) * 2;

    __nv_bfloat16* kb = g_k + (size_t)b * DIM * NSP;
    __nv_bfloat16* vb = g_v + (size_t)b * DIM * NSP;

    int sc_[4], sn_[4];
    #pragma unroll
    for (int j = 0; j < 4; ++j) {
        const int i = tid + j * 512;
        sc_[j] = i >> 4;
        sn_[j] = (i & 15) * 8;
    }

    uint4 r[2][4];
    const int tile0 = blockIdx.x * (KVT * 128);
    #pragma unroll
    for (int j = 0; j < 4; ++j)
        r[0][j] = ldpack8(&cb[(size_t)sc_[j] * NSP + tile0 + sn_[j]]);
    __syncthreads();

    #pragma unroll
    for (int t = 0; t < KVT; ++t) {
        const int n0 = tile0 + t * 128;
        const int cur = t & 1, nxt = cur ^ 1;
        #pragma unroll
        for (int j = 0; j < 4; ++j)
            *reinterpret_cast<uint4*>(&Xs[sc_[j] * 136 + sn_[j]]) = r[cur][j];
        __syncthreads();

        if (t + 1 < KVT) {
            #pragma unroll
            for (int j = 0; j < 4; ++j)
                r[nxt][j] = ldpack8(&cb[(size_t)sc_[j] * NSP + n0 + 128 + sn_[j]]);
        }

        float acc[2][4][4];
        #pragma unroll
        for (int mi = 0; mi < 2; ++mi)
            #pragma unroll
            for (int nf = 0; nf < 4; ++nf)
                #pragma unroll
                for (int e = 0; e < 4; ++e) acc[mi][nf][e] = 0.f;

        #pragma unroll
        for (int kc = 0; kc < 8; ++kc) {
            uint32_t a[2][4];
            ldsm4(a[0][0], a[0][1], a[0][2], a[0][3], aBase[0] + kc * 32);
            ldsm4(a[1][0], a[1][1], a[1][2], a[1][3], aBase[1] + kc * 32);
            #pragma unroll
            for (int nfp = 0; nfp < 2; ++nfp) {
                uint32_t b0, b1, b2, b3;
                ldsm4t(b0, b1, b2, b3, bBase + kc * 4352 + nfp * 32);
                mma16816(acc[0][2 * nfp],     a[0], b0, b1);
                mma16816(acc[1][2 * nfp],     a[1], b0, b1);
                mma16816(acc[0][2 * nfp + 1], a[0], b2, b3);
                mma16816(acc[1][2 * nfp + 1], a[1], b2, b3);
            }
        }
        __syncthreads();   // all Xs reads done before stsm clobbers it

        #pragma unroll
        for (int mi = 0; mi < 2; ++mi) {
            const int m = mw * 32 + mi * 16 + lr;
            const float bi0 = bs[m], bi1 = bs[m + 8];
            #pragma unroll
            for (int nfp = 0; nfp < 2; ++nfp) {
                stsm4(oBase[mi] + nfp * 32,
                      packbf(acc[mi][2*nfp][0] + bi0,   acc[mi][2*nfp][1] + bi0),
                      packbf(acc[mi][2*nfp][2] + bi1,   acc[mi][2*nfp][3] + bi1),
                      packbf(acc[mi][2*nfp+1][0] + bi0, acc[mi][2*nfp+1][1] + bi0),
                      packbf(acc[mi][2*nfp+1][2] + bi1, acc[mi][2*nfp+1][3] + bi1));
            }
        }
        __syncthreads();

        #pragma unroll
        for (int i = tid; i < 128 * 16; i += 512) {
            const int row = i >> 4, q8 = (i & 15) * 8;
            uint4 v = *reinterpret_cast<const uint4*>(&Xs[row * 136 + q8]);
            __nv_bfloat16* dst = (row < 64) ? (kb + (size_t)row * NSP)
                                            : (vb + (size_t)(row - 64) * NSP);
            *reinterpret_cast<uint4*>(&dst[n0 + q8]) = v;
        }
        __syncthreads();
    }
}

// ---------------------------------------------------------------------------
// Pass 2: attention, 128 thr, 4 d-values per CTA with double-buffered
// cp.async pipeline. Register softmax; Of aliases current buffer's Q+K.
// ---------------------------------------------------------------------------
#define ATTN_D 4
#define ABUF (3 * 64 * 72 * 2)   /* 27648 bytes per buffer */

__device__ __forceinline__ void stage_qkv(uint32_t sQ, uint32_t sK, uint32_t sV,
                                          const char* qg, const char* kg,
                                          const char* vg, int tid) {
    #pragma unroll
    for (int i = tid; i < 512; i += 128) {
        const int h = i >> 3, w8 = (i & 7) * 8;
        const uint32_t soff = (uint32_t)(h * 72 + w8) * 2;
        const int goff = i * 16;
        cpasync16(sQ + soff, qg + goff);
        cpasync16(sK + soff, kg + goff);
        cpasync16(sV + soff, vg + goff);
    }
    asm volatile("cp.async.commit_group;\n");
}

__global__ void __launch_bounds__(128) attn_kernel(
    const float* __restrict__ x, float* __restrict__ out)
{
    __shared__ __align__(16) char smbuf[2][ABUF];

    const int tid = threadIdx.x;
    const int d0 = blockIdx.x * ATTN_D, c = blockIdx.y, b = blockIdx.z;
    const size_t cdbase = ((size_t)b * DIM + c) * DD;

    const uint32_t s0 = smaddr(smbuf[0]);
    const uint32_t s1 = smaddr(smbuf[1]);

    // prologue: stage d0 into buf 0
    {
        const size_t base = (cdbase + d0) * HW;
        stage_qkv(s0, s0 + 9216, s0 + 18432,
                  reinterpret_cast<const char*>(g_q + base),
                  reinterpret_cast<const char*>(g_k + base),
                  reinterpret_cast<const char*>(g_v + base), tid);
    }

    const int warp = tid >> 5, lane = tid & 31;
    const int lr = lane >> 2, lc = lane & 3;
    const int m = warp * 16 + lr;
    const int l8  = lane & 7;
    const int lB1 = (lane >> 3) & 1;
    const int lB2 = (lane >> 4) & 1;

    const uint32_t qOff = ((warp * 16 + lB1 * 8 + l8) * 72 + lB2 * 8) * 2;
    const uint32_t kOff = 9216  + ((lB2 * 8 + l8) * 72 + lB1 * 8) * 2;
    const uint32_t vOff = 18432 + ((lB1 * 8 + l8) * 72 + lB2 * 8) * 2;

    #pragma unroll
    for (int dd = 0; dd < ATTN_D; ++dd) {
        const uint32_t sb = (dd & 1) ? s1 : s0;
        // prefetch next d into the other buffer
        if (dd + 1 < ATTN_D) {
            const uint32_t sn = (dd & 1) ? s0 : s1;
            const size_t nbase = (cdbase + d0 + dd + 1) * HW;
            stage_qkv(sn, sn + 9216, sn + 18432,
                      reinterpret_cast<const char*>(g_q + nbase),
                      reinterpret_cast<const char*>(g_k + nbase),
                      reinterpret_cast<const char*>(g_v + nbase), tid);
            asm volatile("cp.async.wait_group 1;\n");
        } else {
            asm volatile("cp.async.wait_group 0;\n");
        }
        __syncthreads();

        const uint32_t qBase = sb + qOff;
        const uint32_t kBase = sb + kOff;
        const uint32_t vBase = sb + vOff;

        // ---- S = Q K^T ----
        float sacc[8][4];
        #pragma unroll
        for (int nf = 0; nf < 8; ++nf)
            #pragma unroll
            for (int e = 0; e < 4; ++e) sacc[nf][e] = 0.f;

        #pragma unroll
        for (int kc = 0; kc < 4; ++kc) {
            uint32_t a[4];
            ldsm4(a[0], a[1], a[2], a[3], qBase + kc * 32);
            #pragma unroll
            for (int nfp = 0; nfp < 4; ++nfp) {
                uint32_t b0, b1, b2, b3;
                ldsm4(b0, b1, b2, b3, kBase + nfp * 2304 + kc * 32);
                mma16816(sacc[2 * nfp],     a, b0, b1);
                mma16816(sacc[2 * nfp + 1], a, b2, b3);
            }
        }

        // ---- register softmax ----
        const float sc = 0.125f;
        float mx0 = -1e30f, mx1 = -1e30f;
        #pragma unroll
        for (int nf = 0; nf < 8; ++nf) {
            mx0 = fmaxf(mx0, fmaxf(sacc[nf][0], sacc[nf][1]));
            mx1 = fmaxf(mx1, fmaxf(sacc[nf][2], sacc[nf][3]));
        }
        mx0 = fmaxf(mx0, __shfl_xor_sync(0xffffffffu, mx0, 1));
        mx0 = fmaxf(mx0, __shfl_xor_sync(0xffffffffu, mx0, 2));
        mx1 = fmaxf(mx1, __shfl_xor_sync(0xffffffffu, mx1, 1));
        mx1 = fmaxf(mx1, __shfl_xor_sync(0xffffffffu, mx1, 2));

        float sum0 = 0.f, sum1 = 0.f;
        #pragma unroll
        for (int nf = 0; nf < 8; ++nf) {
            sacc[nf][0] = __expf(sc * (sacc[nf][0] - mx0));
            sacc[nf][1] = __expf(sc * (sacc[nf][1] - mx0));
            sacc[nf][2] = __expf(sc * (sacc[nf][2] - mx1));
            sacc[nf][3] = __expf(sc * (sacc[nf][3] - mx1));
            sum0 += sacc[nf][0] + sacc[nf][1];
            sum1 += sacc[nf][2] + sacc[nf][3];
        }
        sum0 += __shfl_xor_sync(0xffffffffu, sum0, 1);
        sum0 += __shfl_xor_sync(0xffffffffu, sum0, 2);
        sum1 += __shfl_xor_sync(0xffffffffu, sum1, 1);
        sum1 += __shfl_xor_sync(0xffffffffu, sum1, 2);
        const float inv0 = 1.0f / sum0, inv1 = 1.0f / sum1;

        uint32_t pf[4][4];
        #pragma unroll
        for (int kc = 0; kc < 4; ++kc) {
            pf[kc][0] = packbf(sacc[2*kc][0] * inv0,   sacc[2*kc][1] * inv0);
            pf[kc][1] = packbf(sacc[2*kc][2] * inv1,   sacc[2*kc][3] * inv1);
            pf[kc][2] = packbf(sacc[2*kc+1][0] * inv0, sacc[2*kc+1][1] * inv0);
            pf[kc][3] = packbf(sacc[2*kc+1][2] * inv1, sacc[2*kc+1][3] * inv1);
        }

        __syncthreads();   // all Q/K reads done before Of overwrite

        float* Of = reinterpret_cast<float*>((dd & 1) ? smbuf[1] : smbuf[0]);

        // ---- O = P V in two nf-halves ----
        #pragma unroll
        for (int half = 0; half < 2; ++half) {
            float oacc[4][4];
            #pragma unroll
            for (int f = 0; f < 4; ++f)
                #pragma unroll
                for (int e = 0; e < 4; ++e) oacc[f][e] = 0.f;

            #pragma unroll
            for (int kc = 0; kc < 4; ++kc) {
                #pragma unroll
                for (int p = 0; p < 2; ++p) {
                    const int nfp = half * 2 + p;
                    uint32_t b0, b1, b2, b3;
                    ldsm4t(b0, b1, b2, b3, vBase + kc * 2304 + nfp * 32);
                    mma16816(oacc[2 * p],     pf[kc], b0, b1);
                    mma16816(oacc[2 * p + 1], pf[kc], b2, b3);
                }
            }
            #pragma unroll
            for (int f = 0; f < 4; ++f) {
                const int n = (half * 4 + f) * 8 + lc * 2;
                *reinterpret_cast<float2*>(&Of[m * 68 + n]) =
                    make_float2(oacc[f][0], oacc[f][1]);
                *reinterpret_cast<float2*>(&Of[(m + 8) * 68 + n]) =
                    make_float2(oacc[f][2], oacc[f][3]);
            }
        }
        __syncthreads();

        // ---- coalesced residual + store ----
        const size_t base = (cdbase + d0 + dd) * HW;
        const float* xb = x + base;
        float* ob = out + base;
        #pragma unroll
        for (int i = tid; i < 64 * 16; i += 128) {
            const int row = i >> 4, q4 = (i & 15) * 4;
            float4 o = *reinterpret_cast<const float4*>(&Of[row * 68 + q4]);
            float4 xr = *reinterpret_cast<const float4*>(&xb[row * 64 + q4]);
            o.x += xr.x; o.y += xr.y; o.z += xr.z; o.w += xr.w;
            *reinterpret_cast<float4*>(&ob[row * 64 + q4]) = o;
        }
        __syncthreads();   // Of fully consumed before next iter's stage into this buf
    }
}

// ---------------------------------------------------------------------------
extern "C" void kernel_launch(void* const* d_in, const int* in_sizes, int n_in,
                              void* d_out, int out_size)
{
    const float* x   = (const float*)d_in[0];
    const float* ctx = (const float*)d_in[1];
    const float* wq  = (const float*)d_in[2];
    const float* bq  = (const float*)d_in[3];
    const float* wk  = (const float*)d_in[4];
    const float* bk  = (const float*)d_in[5];
    const float* wv  = (const float*)d_in[6];
    const float* bv  = (const float*)d_in[7];
    float* out = (float*)d_out;

    conv_q_kernel<<<dim3(NSP / (QT * 128), BB), 256>>>(x, wq, bq);

    cudaFuncSetAttribute(conv_kv_kernel,
                         cudaFuncAttributeMaxDynamicSharedMemorySize,
                         KV_SMEM_BYTES);
    conv_kv_kernel<<<dim3(NSP / (KVT * 128), BB), 512, KV_SMEM_BYTES>>>(
        ctx, wk, bk, wv, bv);

    attn_kernel<<<dim3(DD / ATTN_D, DIM, BB), 128>>>(x, out);
}